// round 12
// baseline (speedup 1.0000x reference)
#include <cuda_runtime.h>

#define NN 2048
#define NE 32768
#define DF 2048
#define TOPK 20
#define RMAXF 1e-5f
#define ROWS 4
#define NTILES 512
#define NTHREADS 512
#define GRID 296
#define LISTCAP 1024
#define SPARSE_T 192
#define MAXIT 500
#define NGRP 64              // 64 groups x 32 columns

// ---------------- device scratch ----------------
__device__ int g_deg[NN], g_indeg[NN];
__device__ int g_rowptr[NN + 1], g_colptr[NN + 1];
__device__ int g_fillr[NN], g_fillc[NN];
__device__ float g_halfinv[NN];
__device__ int g_dst[NE];        // CSR out-edges (per-row sorted)
__device__ int g_srcCSC[NE];     // CSC in-edges (bank-staggered order)
__device__ int g_perm[NN];       // columns sorted by in-degree (ascending)
__device__ int g_ppos[NN];       // inverse perm
__device__ int g_ellbase[NGRP + 1];
__device__ unsigned short g_ell[262144];   // [grp][p][lane] = src<<4 (pad=2048<<4)
__device__ int g_work;

// ---------------- setup ----------------
__global__ void k_zero() {
    int i = blockIdx.x * 256 + threadIdx.x;
    if (i < NN) { g_deg[i] = 0; g_indeg[i] = 0; g_fillr[i] = 0; g_fillc[i] = 0; }
    if (i == 0) g_work = 0;
}

__global__ void k_count(const int* __restrict__ ei) {
    int e = blockIdx.x * 256 + threadIdx.x;
    if (e >= NE) return;
    atomicAdd(&g_deg[ei[e]], 1);
    atomicAdd(&g_indeg[ei[NE + e]], 1);
}

__global__ void __launch_bounds__(256) k_scanperm() {
    __shared__ int s[256];
    __shared__ int hist[64], hb[64];
    const int t = threadIdx.x;
    if (t < 64) hist[t] = 0;
    for (int pass = 0; pass < 2; pass++) {
        const int* cnt = pass ? g_deg : g_indeg;
        int* ptr = pass ? g_rowptr : g_colptr;
        int base = t * 8;
        int v[8]; int sum = 0;
#pragma unroll
        for (int m = 0; m < 8; m++) { v[m] = cnt[base + m]; sum += v[m]; }
        s[t] = sum; __syncthreads();
        for (int off = 1; off < 256; off <<= 1) {
            int x = (t >= off) ? s[t - off] : 0;
            __syncthreads();
            s[t] += x;
            __syncthreads();
        }
        int excl = (t == 0) ? 0 : s[t - 1];
#pragma unroll
        for (int m = 0; m < 8; m++) { ptr[base + m] = excl; excl += v[m]; }
        if (t == 255) ptr[NN] = excl;
        __syncthreads();
    }
    for (int k = t; k < NN; k += 256) {
        int d = g_deg[k];
        g_halfinv[k] = 0.5f / (d ? (float)d : 1.f);
        atomicAdd(&hist[min(g_indeg[k], 63)], 1);
    }
    __syncthreads();
    if (t == 0) { int acc = 0; for (int b = 0; b < 64; b++) { hb[b] = acc; acc += hist[b]; } }
    __syncthreads();
    for (int k = t; k < NN; k += 256) {
        int pos = atomicAdd(&hb[min(g_indeg[k], 63)], 1);
        g_perm[pos] = k;
        g_ppos[k] = pos;
    }
    __syncthreads();
    if (t == 0) {
        int acc = 0;
        for (int g = 0; g < NGRP; g++) {
            g_ellbase[g] = acc;
            acc += 32 * g_indeg[g_perm[g * 32 + 31]];
        }
        g_ellbase[NGRP] = acc;
    }
}

__global__ void k_fill(const int* __restrict__ ei) {
    int e = blockIdx.x * 256 + threadIdx.x;
    if (e >= NE) return;
    int r = ei[e], c = ei[NE + e];
    int pr = atomicAdd(&g_fillr[r], 1);
    g_dst[g_rowptr[r] + pr] = c;
    int pc = atomicAdd(&g_fillc[c], 1);
    g_srcCSC[g_colptr[c] + pc] = r;
}

__global__ void k_build() {
    int id = blockIdx.x * blockDim.x + threadIdx.x;
    if (id >= 2 * NN) return;
    if (id < NN) {
        // Bank-staggered deterministic order: lanes of the same start-class
        // consume distinct bank-groups (src&7) at each ELL step.
        int p0 = g_colptr[id], p1 = g_colptr[id + 1];
        int pos = g_ppos[id];
        int lane = pos & 31;
        int sc = lane >> 2;   // start class 0..7
        for (int i = p0 + 1; i < p1; i++) {
            int x = g_srcCSC[i];
            int kx = (((x & 7) - sc) & 7);
            int j = i - 1;
            while (j >= p0) {
                int y = g_srcCSC[j];
                int ky = (((y & 7) - sc) & 7);
                if (ky > kx || (ky == kx && y > x)) { g_srcCSC[j + 1] = y; j--; }
                else break;
            }
            g_srcCSC[j + 1] = x;
        }
        int deg = p1 - p0;
        int g = pos >> 5;
        int base = g_ellbase[g];
        int gm = (g_ellbase[g + 1] - base) >> 5;
        for (int p = 0; p < gm; p++)
            g_ell[base + (p << 5) + lane] =
                (p < deg) ? (unsigned short)(g_srcCSC[p0 + p] << 4)
                          : (unsigned short)(2048 << 4);
    } else {
        int r = id - NN;
        int p0 = g_rowptr[r], p1 = g_rowptr[r + 1];
        for (int i = p0 + 1; i < p1; i++) {
            int x = g_dst[i]; int j = i - 1;
            while (j >= p0 && g_dst[j] > x) { g_dst[j + 1] = g_dst[j]; j--; }
            g_dst[j + 1] = x;
        }
    }
}

// ---------------- persistent push + fused topk/output ----------------
__global__ void __launch_bounds__(NTHREADS, 2)
k_push(const float* __restrict__ X, float* __restrict__ out) {
    extern __shared__ float sh[];
    float* pv = sh;                      // [8196] masked push*(0.5/deg); [8192..]=0 pad
    float* cur = pv + ROWS * NN + 4;     // [8192] residual
    float* Pp = cur + ROWS * NN;         // [8192] P accumulator
    float* shh = Pp + ROWS * NN;         // [2048] 0.5/deg
    int* lk = (int*)(shh + NN);          // [LISTCAP] frontier entries
    __shared__ int s_cnt, s_lc, s_tile;
    __shared__ float s_redv[16];
    __shared__ int s_redi[16];
    __shared__ float s_tv[ROWS][TOPK];
    __shared__ int s_ti[ROWS][TOPK];

    float4* pv4 = (float4*)pv;
    float4* cur4 = (float4*)cur;
    float4* Pp4 = (float4*)Pp;

    const int tid = threadIdx.x;
    const int lane = tid & 31;
    const int wid = tid >> 5;

    for (int k = tid; k < NN; k += NTHREADS) shh[k] = g_halfinv[k];

    while (true) {
        __syncthreads();
        if (tid == 0) s_tile = atomicAdd(&g_work, 1);
        __syncthreads();
        const int t = s_tile;
        if (t >= NTILES) break;
        const int row0 = t * ROWS;

        // ---- init tile state
        if (tid == 0) pv4[2048] = make_float4(0.f, 0.f, 0.f, 0.f);  // ELL pad target
#pragma unroll
        for (int m = 0; m < NN / NTHREADS; m++) {
            int j = tid + NTHREADS * m;
            float4 z = make_float4(0.f, 0.f, 0.f, 0.f);
            Pp4[j] = z;
            int d = j - row0;
            if (d >= 0 && d < ROWS) ((float*)&z)[d] = 1.f;
            cur4[j] = z;
        }

        for (int iter = 0; iter < MAXIT; iter++) {
            if (tid == 0) { s_cnt = 0; s_lc = 0; }
            __syncthreads();

            // ---- phase A: mask, write pv, update P, zero pushed, count,
            //      AND compact frontier inline (ballot per row-slot)
            int c = 0;
#pragma unroll
            for (int m = 0; m < NN / NTHREADS; m++) {
                int j = tid + NTHREADS * m;
                float4 v = cur4[j];
                float h = shh[j];
                bool px = v.x >= RMAXF, py = v.y >= RMAXF,
                     pz = v.z >= RMAXF, pw = v.w >= RMAXF;
                pv4[j] = make_float4(px ? v.x * h : 0.f, py ? v.y * h : 0.f,
                                     pz ? v.z * h : 0.f, pw ? v.w * h : 0.f);
                if (px | py | pz | pw) {
                    float4 p = Pp4[j];
                    if (px) { p.x += 0.5f * v.x; v.x = 0.f; c++; }
                    if (py) { p.y += 0.5f * v.y; v.y = 0.f; c++; }
                    if (pz) { p.z += 0.5f * v.z; v.z = 0.f; c++; }
                    if (pw) { p.w += 0.5f * v.w; v.w = 0.f; c++; }
                    Pp4[j] = p;
                    cur4[j] = v;
                }
                bool pr[4] = {px, py, pz, pw};
#pragma unroll
                for (int r = 0; r < 4; r++) {
                    unsigned msk = __ballot_sync(0xffffffffu, pr[r]);
                    if (msk) {
                        int base = 0;
                        if (lane == 0) base = atomicAdd(&s_lc, __popc(msk));
                        base = __shfl_sync(0xffffffffu, base, 0);
                        if (pr[r]) {
                            int pos = base + __popc(msk & ((1u << lane) - 1));
                            if (pos < LISTCAP) lk[pos] = (j << 2) | r;
                        }
                    }
                }
            }
            c = __reduce_add_sync(0xffffffffu, c);
            if (lane == 0 && c) atomicAdd(&s_cnt, c);
            __syncthreads();
            const int cnt = s_cnt;
            if (cnt == 0) break;

            if (cnt > SPARSE_T) {
                // ---- dense: ELL gather (coalesced LDG.U16 + bank-staggered LDS.128)
#pragma unroll
                for (int m = 0; m < NGRP / (NTHREADS / 32); m++) {
                    int g = wid + (NTHREADS / 32) * m;
                    int jr = __ldg(&g_perm[(g << 5) + lane]);
                    int base = __ldg(&g_ellbase[g]);
                    int gm = (__ldg(&g_ellbase[g + 1]) - base) >> 5;
                    const unsigned short* ep = g_ell + base + lane;
                    float4 acc = cur4[jr];
#pragma unroll 4
                    for (int p = 0; p < gm; p++) {
                        int off = ep[p << 5];
                        float4 v = *(const float4*)((const char*)pv + off);
                        acc.x += v.x; acc.y += v.y; acc.z += v.z; acc.w += v.w;
                    }
                    cur4[jr] = acc;
                }
                __syncthreads();
            } else {
                // ---- sparse: CSR scatter of pre-built frontier
                for (int l = tid; l < cnt; l += NTHREADS) {
                    int e = lk[l], k = e >> 2, r = e & 3;
                    float w = pv[e];
                    int p1 = __ldg(&g_rowptr[k + 1]);
                    for (int p = __ldg(&g_rowptr[k]); p < p1; p++)
                        atomicAdd(&cur[(__ldg(&g_dst[p]) << 2) | r], w);
                }
                __syncthreads();
            }
        }
        __syncthreads();

        // ---- fused top-k per row (128 threads per row)
        const int rg = tid >> 7;
        const int tl = tid & 127;
        for (int q = 0; q < TOPK; q++) {
            float bv = -1.f; int bi = NN;
#pragma unroll
            for (int m = 0; m < NN / 128; m++) {
                int j = tl + 128 * m;
                float v = Pp[(j << 2) | rg];
                if (v > bv || (v == bv && j < bi)) { bv = v; bi = j; }
            }
#pragma unroll
            for (int off = 16; off; off >>= 1) {
                float ov = __shfl_down_sync(0xffffffffu, bv, off);
                int oi = __shfl_down_sync(0xffffffffu, bi, off);
                if (ov > bv || (ov == bv && oi < bi)) { bv = ov; bi = oi; }
            }
            if (lane == 0) { s_redv[wid] = bv; s_redi[wid] = bi; }
            __syncthreads();
            if (tl == 0) {
                float v0 = s_redv[4 * rg]; int i0 = s_redi[4 * rg];
#pragma unroll
                for (int w = 1; w < 4; w++) {
                    float v1 = s_redv[4 * rg + w]; int i1 = s_redi[4 * rg + w];
                    if (v1 > v0 || (v1 == v0 && i1 < i0)) { v0 = v1; i0 = i1; }
                }
                s_tv[rg][q] = v0; s_ti[rg][q] = i0;
                Pp[(i0 << 2) | rg] = -2.f;
            }
            __syncthreads();
        }

        // ---- output GEMV
        const float4* X4 = (const float4*)X;
        float4* out4 = (float4*)out;
#pragma unroll
        for (int m = 0; m < DF / 4 / 128; m++) {
            int col = tl + 128 * m;
            float4 acc = make_float4(0.f, 0.f, 0.f, 0.f);
#pragma unroll
            for (int q = 0; q < TOPK; q++) {
                float w = s_tv[rg][q];
                float4 x = __ldg(&X4[(size_t)s_ti[rg][q] * (DF / 4) + col]);
                acc.x += w * x.x; acc.y += w * x.y;
                acc.z += w * x.z; acc.w += w * x.w;
            }
            out4[(size_t)(row0 + rg) * (DF / 4) + col] = acc;
        }
    }
}

// ---------------- launch ----------------
extern "C" void kernel_launch(void* const* d_in, const int* in_sizes, int n_in,
                              void* d_out, int out_size) {
    const float* X;
    const int* ei;
    if (in_sizes[0] == 2 * NE) { ei = (const int*)d_in[0]; X = (const float*)d_in[1]; }
    else { X = (const float*)d_in[0]; ei = (const int*)d_in[1]; }
    float* out = (float*)d_out;

    const int smem = (ROWS * NN + 4 + 2 * ROWS * NN + NN) * sizeof(float)
                   + LISTCAP * sizeof(int);   // ~110.6 KB -> 2 CTAs/SM
    cudaFuncSetAttribute(k_push, cudaFuncAttributeMaxDynamicSharedMemorySize, smem);

    k_zero<<<(NN + 255) / 256, 256>>>();
    k_count<<<NE / 256, 256>>>(ei);
    k_scanperm<<<1, 256>>>();
    k_fill<<<NE / 256, 256>>>(ei);
    k_build<<<16, 256>>>();
    k_push<<<GRID, NTHREADS, smem>>>(X, out);
}

// round 13
// speedup vs baseline: 1.1225x; 1.1225x over previous
#include <cuda_runtime.h>

#define NN 2048
#define NE 32768
#define DF 2048
#define TOPK 20
#define RMAXF 1e-5f
#define ROWS 4
#define NTILES 512
#define NTHREADS 512
#define GRID 296
#define LISTCAP 1024
#define SPARSE_T 768
#define MAXIT 500
#define NGRP 64              // 64 groups x 32 columns

// ---------------- device scratch ----------------
__device__ int g_deg[NN], g_indeg[NN];
__device__ int g_rowptr[NN + 1], g_colptr[NN + 1];
__device__ int g_fillr[NN], g_fillc[NN];
__device__ float g_halfinv[NN];
__device__ int g_dst[NE];        // CSR out-edges (per-row sorted)
__device__ int g_srcCSC[NE];     // CSC in-edges (per-col ascending)
__device__ int g_perm[NN];       // columns sorted by in-degree (ascending)
__device__ int g_ppos[NN];       // inverse perm
__device__ int g_ellbase[NGRP + 1];
__device__ unsigned short g_ell[262144];   // [grp][p][lane] = src<<4 (pad=2048<<4)
__device__ int g_work;

// ---------------- setup ----------------
__global__ void k_zero() {
    int i = blockIdx.x * 256 + threadIdx.x;
    if (i < NN) { g_deg[i] = 0; g_indeg[i] = 0; g_fillr[i] = 0; g_fillc[i] = 0; }
    if (i == 0) g_work = 0;
}

__global__ void k_count(const int* __restrict__ ei) {
    int e = blockIdx.x * 256 + threadIdx.x;
    if (e >= NE) return;
    atomicAdd(&g_deg[ei[e]], 1);
    atomicAdd(&g_indeg[ei[NE + e]], 1);
}

__global__ void __launch_bounds__(256) k_scanperm() {
    __shared__ int s[256];
    __shared__ int hist[64], hb[64];
    const int t = threadIdx.x;
    if (t < 64) hist[t] = 0;
    for (int pass = 0; pass < 2; pass++) {
        const int* cnt = pass ? g_deg : g_indeg;
        int* ptr = pass ? g_rowptr : g_colptr;
        int base = t * 8;
        int v[8]; int sum = 0;
#pragma unroll
        for (int m = 0; m < 8; m++) { v[m] = cnt[base + m]; sum += v[m]; }
        s[t] = sum; __syncthreads();
        for (int off = 1; off < 256; off <<= 1) {
            int x = (t >= off) ? s[t - off] : 0;
            __syncthreads();
            s[t] += x;
            __syncthreads();
        }
        int excl = (t == 0) ? 0 : s[t - 1];
#pragma unroll
        for (int m = 0; m < 8; m++) { ptr[base + m] = excl; excl += v[m]; }
        if (t == 255) ptr[NN] = excl;
        __syncthreads();
    }
    for (int k = t; k < NN; k += 256) {
        int d = g_deg[k];
        g_halfinv[k] = 0.5f / (d ? (float)d : 1.f);
        atomicAdd(&hist[min(g_indeg[k], 63)], 1);
    }
    __syncthreads();
    if (t == 0) { int acc = 0; for (int b = 0; b < 64; b++) { hb[b] = acc; acc += hist[b]; } }
    __syncthreads();
    for (int k = t; k < NN; k += 256) {
        int pos = atomicAdd(&hb[min(g_indeg[k], 63)], 1);
        g_perm[pos] = k;
        g_ppos[k] = pos;
    }
    __syncthreads();
    if (t == 0) {
        int acc = 0;
        for (int g = 0; g < NGRP; g++) {
            g_ellbase[g] = acc;
            acc += 32 * g_indeg[g_perm[g * 32 + 31]];
        }
        g_ellbase[NGRP] = acc;
    }
}

__global__ void k_fill(const int* __restrict__ ei) {
    int e = blockIdx.x * 256 + threadIdx.x;
    if (e >= NE) return;
    int r = ei[e], c = ei[NE + e];
    int pr = atomicAdd(&g_fillr[r], 1);
    g_dst[g_rowptr[r] + pr] = c;
    int pc = atomicAdd(&g_fillc[c], 1);
    g_srcCSC[g_colptr[c] + pc] = r;
}

__global__ void k_build() {
    int id = blockIdx.x * blockDim.x + threadIdx.x;
    if (id >= 2 * NN) return;
    if (id < NN) {
        // ascending sort (deterministic base order)
        int p0 = g_colptr[id], p1 = g_colptr[id + 1];
        for (int i = p0 + 1; i < p1; i++) {
            int x = g_srcCSC[i]; int j = i - 1;
            while (j >= p0 && g_srcCSC[j] > x) { g_srcCSC[j + 1] = g_srcCSC[j]; j--; }
            g_srcCSC[j + 1] = x;
        }
        int deg = p1 - p0;
        int pos = g_ppos[id];
        int g = pos >> 5, lane = pos & 31;
        int sc = lane >> 2;                // lane's bank start-class 0..7
        // bucket by bank-group (src&7), ascending within bucket
        int cnt8[8] = {0, 0, 0, 0, 0, 0, 0, 0};
        for (int i = 0; i < deg; i++) cnt8[g_srcCSC[p0 + i] & 7]++;
        int st[9]; st[0] = 0;
        for (int b = 0; b < 8; b++) st[b + 1] = st[b] + cnt8[b];
        int buf[64];
        int fill[8];
        for (int b = 0; b < 8; b++) fill[b] = st[b];
        for (int i = 0; i < deg && i < 64; i++) {
            int sv = g_srcCSC[p0 + i];
            buf[fill[sv & 7]++] = sv;
        }
        int ptr8[8];
        for (int b = 0; b < 8; b++) ptr8[b] = st[b];
        int base = g_ellbase[g];
        int gm = (g_ellbase[g + 1] - base) >> 5;
        // cyclic emission: step p prefers bank-group (sc+p)&7
        for (int p = 0; p < gm; p++) {
            unsigned short v = (unsigned short)(2048 << 4);
            if (p < deg) {
                int b0 = (sc + p) & 7;
                for (int q = 0; q < 8; q++) {
                    int b = (b0 + q) & 7;
                    if (ptr8[b] < st[b + 1]) { v = (unsigned short)(buf[ptr8[b]++] << 4); break; }
                }
            }
            g_ell[base + (p << 5) + lane] = v;
        }
    } else {
        int r = id - NN;
        int p0 = g_rowptr[r], p1 = g_rowptr[r + 1];
        for (int i = p0 + 1; i < p1; i++) {
            int x = g_dst[i]; int j = i - 1;
            while (j >= p0 && g_dst[j] > x) { g_dst[j + 1] = g_dst[j]; j--; }
            g_dst[j + 1] = x;
        }
    }
}

// ---------------- persistent push + fused topk/output ----------------
__global__ void __launch_bounds__(NTHREADS, 2)
k_push(const float* __restrict__ X, float* __restrict__ out) {
    extern __shared__ float sh[];
    float* pv = sh;                      // [8196] masked push*(0.5/deg); [8192..]=0 pad
    float* cur = pv + ROWS * NN + 4;     // [8192] residual
    float* Pp = cur + ROWS * NN;         // [8192] P accumulator
    float* shh = Pp + ROWS * NN;         // [2048] 0.5/deg
    int* lk = (int*)(shh + NN);          // [LISTCAP] frontier entries
    __shared__ int s_lc, s_tile;
    __shared__ float s_redv[16];
    __shared__ int s_redi[16];
    __shared__ float s_tv[ROWS][TOPK];
    __shared__ int s_ti[ROWS][TOPK];

    float4* pv4 = (float4*)pv;
    float4* cur4 = (float4*)cur;
    float4* Pp4 = (float4*)Pp;

    const int tid = threadIdx.x;
    const int lane = tid & 31;
    const int wid = tid >> 5;

    for (int k = tid; k < NN; k += NTHREADS) shh[k] = g_halfinv[k];

    while (true) {
        __syncthreads();
        if (tid == 0) s_tile = atomicAdd(&g_work, 1);
        __syncthreads();
        const int t = s_tile;
        if (t >= NTILES) break;
        const int row0 = t * ROWS;

        // ---- init tile state
        if (tid == 0) pv4[2048] = make_float4(0.f, 0.f, 0.f, 0.f);  // ELL pad target
#pragma unroll
        for (int m = 0; m < NN / NTHREADS; m++) {
            int j = tid + NTHREADS * m;
            float4 z = make_float4(0.f, 0.f, 0.f, 0.f);
            Pp4[j] = z;
            int d = j - row0;
            if (d >= 0 && d < ROWS) ((float*)&z)[d] = 1.f;
            cur4[j] = z;
        }

        for (int iter = 0; iter < MAXIT; iter++) {
            if (tid == 0) s_lc = 0;
            __syncthreads();

            // ---- phase A: mask, write pv, update P, zero pushed,
            //      compact frontier inline; s_lc accumulates total pushes
            int c = 0;
#pragma unroll
            for (int m = 0; m < NN / NTHREADS; m++) {
                int j = tid + NTHREADS * m;
                float4 v = cur4[j];
                float h = shh[j];
                bool px = v.x >= RMAXF, py = v.y >= RMAXF,
                     pz = v.z >= RMAXF, pw = v.w >= RMAXF;
                pv4[j] = make_float4(px ? v.x * h : 0.f, py ? v.y * h : 0.f,
                                     pz ? v.z * h : 0.f, pw ? v.w * h : 0.f);
                if (px | py | pz | pw) {
                    float4 p = Pp4[j];
                    if (px) { p.x += 0.5f * v.x; v.x = 0.f; }
                    if (py) { p.y += 0.5f * v.y; v.y = 0.f; }
                    if (pz) { p.z += 0.5f * v.z; v.z = 0.f; }
                    if (pw) { p.w += 0.5f * v.w; v.w = 0.f; }
                    Pp4[j] = p;
                    cur4[j] = v;
                }
                bool pr[4] = {px, py, pz, pw};
#pragma unroll
                for (int r = 0; r < 4; r++) {
                    unsigned msk = __ballot_sync(0xffffffffu, pr[r]);
                    if (msk) {
                        int base = 0;
                        if (lane == 0) base = atomicAdd(&s_lc, __popc(msk));
                        base = __shfl_sync(0xffffffffu, base, 0);
                        if (pr[r]) {
                            int pos = base + __popc(msk & ((1u << lane) - 1));
                            if (pos < LISTCAP) lk[pos] = (j << 2) | r;
                        }
                    }
                }
            }
            (void)c;
            __syncthreads();
            const int cnt = s_lc;
            if (cnt == 0) break;

            if (cnt > SPARSE_T) {
                // ---- dense: ELL gather (coalesced LDG.U16 + bank-rotated LDS.128)
#pragma unroll
                for (int m = 0; m < NGRP / (NTHREADS / 32); m++) {
                    int g = wid + (NTHREADS / 32) * m;
                    int jr = __ldg(&g_perm[(g << 5) + lane]);
                    int base = __ldg(&g_ellbase[g]);
                    int gm = (__ldg(&g_ellbase[g + 1]) - base) >> 5;
                    const unsigned short* ep = g_ell + base + lane;
                    float4 acc = cur4[jr];
#pragma unroll 4
                    for (int p = 0; p < gm; p++) {
                        int off = ep[p << 5];
                        float4 v = *(const float4*)((const char*)pv + off);
                        acc.x += v.x; acc.y += v.y; acc.z += v.z; acc.w += v.w;
                    }
                    cur4[jr] = acc;
                }
                __syncthreads();
            } else {
                // ---- sparse: CSR scatter of pre-built frontier
                for (int l = tid; l < cnt; l += NTHREADS) {
                    int e = lk[l], k = e >> 2, r = e & 3;
                    float w = pv[e];
                    int p1 = __ldg(&g_rowptr[k + 1]);
                    for (int p = __ldg(&g_rowptr[k]); p < p1; p++)
                        atomicAdd(&cur[(__ldg(&g_dst[p]) << 2) | r], w);
                }
                __syncthreads();
            }
        }
        __syncthreads();

        // ---- fused top-k per row (128 threads per row)
        const int rg = tid >> 7;
        const int tl = tid & 127;
        for (int q = 0; q < TOPK; q++) {
            float bv = -1.f; int bi = NN;
#pragma unroll
            for (int m = 0; m < NN / 128; m++) {
                int j = tl + 128 * m;
                float v = Pp[(j << 2) | rg];
                if (v > bv || (v == bv && j < bi)) { bv = v; bi = j; }
            }
#pragma unroll
            for (int off = 16; off; off >>= 1) {
                float ov = __shfl_down_sync(0xffffffffu, bv, off);
                int oi = __shfl_down_sync(0xffffffffu, bi, off);
                if (ov > bv || (ov == bv && oi < bi)) { bv = ov; bi = oi; }
            }
            if (lane == 0) { s_redv[wid] = bv; s_redi[wid] = bi; }
            __syncthreads();
            if (tl == 0) {
                float v0 = s_redv[4 * rg]; int i0 = s_redi[4 * rg];
#pragma unroll
                for (int w = 1; w < 4; w++) {
                    float v1 = s_redv[4 * rg + w]; int i1 = s_redi[4 * rg + w];
                    if (v1 > v0 || (v1 == v0 && i1 < i0)) { v0 = v1; i0 = i1; }
                }
                s_tv[rg][q] = v0; s_ti[rg][q] = i0;
                Pp[(i0 << 2) | rg] = -2.f;
            }
            __syncthreads();
        }

        // ---- output GEMV
        const float4* X4 = (const float4*)X;
        float4* out4 = (float4*)out;
#pragma unroll
        for (int m = 0; m < DF / 4 / 128; m++) {
            int col = tl + 128 * m;
            float4 acc = make_float4(0.f, 0.f, 0.f, 0.f);
#pragma unroll
            for (int q = 0; q < TOPK; q++) {
                float w = s_tv[rg][q];
                float4 x = __ldg(&X4[(size_t)s_ti[rg][q] * (DF / 4) + col]);
                acc.x += w * x.x; acc.y += w * x.y;
                acc.z += w * x.z; acc.w += w * x.w;
            }
            out4[(size_t)(row0 + rg) * (DF / 4) + col] = acc;
        }
    }
}

// ---------------- launch ----------------
extern "C" void kernel_launch(void* const* d_in, const int* in_sizes, int n_in,
                              void* d_out, int out_size) {
    const float* X;
    const int* ei;
    if (in_sizes[0] == 2 * NE) { ei = (const int*)d_in[0]; X = (const float*)d_in[1]; }
    else { X = (const float*)d_in[0]; ei = (const int*)d_in[1]; }
    float* out = (float*)d_out;

    const int smem = (ROWS * NN + 4 + 2 * ROWS * NN + NN) * sizeof(float)
                   + LISTCAP * sizeof(int);   // ~110.6 KB -> 2 CTAs/SM
    cudaFuncSetAttribute(k_push, cudaFuncAttributeMaxDynamicSharedMemorySize, smem);

    k_zero<<<(NN + 255) / 256, 256>>>();
    k_count<<<NE / 256, 256>>>(ei);
    k_scanperm<<<1, 256>>>();
    k_fill<<<NE / 256, 256>>>(ei);
    k_build<<<16, 256>>>();
    k_push<<<GRID, NTHREADS, smem>>>(X, out);
}

// round 15
// speedup vs baseline: 1.1948x; 1.0644x over previous
#include <cuda_runtime.h>

#define NN 2048
#define NE 32768
#define DF 2048
#define TOPK 20
#define RMAXF 1e-5f
#define ROWS 4
#define NTILES 512
#define NTHREADS 512
#define GRID 296
#define LISTCAP 1024
#define CCAP 8192
#define SPARSE_T 768
#define MAXIT 500
#define NGRP 64              // 64 groups x 32 columns

// ---------------- device scratch ----------------
__device__ int g_deg[NN], g_indeg[NN];
__device__ int g_rowptr[NN + 1], g_colptr[NN + 1];
__device__ int g_fillr[NN], g_fillc[NN];
__device__ float g_halfinv[NN];
__device__ int g_dst[NE];        // CSR out-edges (per-row sorted)
__device__ int g_srcCSC[NE];     // CSC in-edges (per-col ascending)
__device__ int g_perm[NN];       // columns sorted by in-degree (ascending)
__device__ int g_ppos[NN];       // inverse perm
__device__ int g_ellbase[NGRP + 1];
__device__ unsigned short g_ell[262144];   // [grp][p][lane] = src<<4 (pad=2048<<4)
__device__ int g_work;

// ---------------- setup ----------------
__global__ void k_zero() {
    int i = blockIdx.x * 256 + threadIdx.x;
    if (i < NN) { g_deg[i] = 0; g_indeg[i] = 0; g_fillr[i] = 0; g_fillc[i] = 0; }
    if (i == 0) g_work = 0;
}

__global__ void k_count(const int* __restrict__ ei) {
    int e = blockIdx.x * 256 + threadIdx.x;
    if (e >= NE) return;
    atomicAdd(&g_deg[ei[e]], 1);
    atomicAdd(&g_indeg[ei[NE + e]], 1);
}

__global__ void __launch_bounds__(256) k_scanperm() {
    __shared__ int s[256];
    __shared__ int hist[64], hb[64];
    const int t = threadIdx.x;
    if (t < 64) hist[t] = 0;
    for (int pass = 0; pass < 2; pass++) {
        const int* cnt = pass ? g_deg : g_indeg;
        int* ptr = pass ? g_rowptr : g_colptr;
        int base = t * 8;
        int v[8]; int sum = 0;
#pragma unroll
        for (int m = 0; m < 8; m++) { v[m] = cnt[base + m]; sum += v[m]; }
        s[t] = sum; __syncthreads();
        for (int off = 1; off < 256; off <<= 1) {
            int x = (t >= off) ? s[t - off] : 0;
            __syncthreads();
            s[t] += x;
            __syncthreads();
        }
        int excl = (t == 0) ? 0 : s[t - 1];
#pragma unroll
        for (int m = 0; m < 8; m++) { ptr[base + m] = excl; excl += v[m]; }
        if (t == 255) ptr[NN] = excl;
        __syncthreads();
    }
    for (int k = t; k < NN; k += 256) {
        int d = g_deg[k];
        g_halfinv[k] = 0.5f / (d ? (float)d : 1.f);
        atomicAdd(&hist[min(g_indeg[k], 63)], 1);
    }
    __syncthreads();
    if (t == 0) { int acc = 0; for (int b = 0; b < 64; b++) { hb[b] = acc; acc += hist[b]; } }
    __syncthreads();
    for (int k = t; k < NN; k += 256) {
        int pos = atomicAdd(&hb[min(g_indeg[k], 63)], 1);
        g_perm[pos] = k;
        g_ppos[k] = pos;
    }
    __syncthreads();
    if (t == 0) {
        int acc = 0;
        for (int g = 0; g < NGRP; g++) {
            g_ellbase[g] = acc;
            acc += 32 * g_indeg[g_perm[g * 32 + 31]];
        }
        g_ellbase[NGRP] = acc;
    }
}

__global__ void k_fill(const int* __restrict__ ei) {
    int e = blockIdx.x * 256 + threadIdx.x;
    if (e >= NE) return;
    int r = ei[e], c = ei[NE + e];
    int pr = atomicAdd(&g_fillr[r], 1);
    g_dst[g_rowptr[r] + pr] = c;
    int pc = atomicAdd(&g_fillc[c], 1);
    g_srcCSC[g_colptr[c] + pc] = r;
}

__global__ void k_build() {
    int id = blockIdx.x * blockDim.x + threadIdx.x;
    if (id >= 2 * NN) return;
    if (id < NN) {
        int p0 = g_colptr[id], p1 = g_colptr[id + 1];
        for (int i = p0 + 1; i < p1; i++) {
            int x = g_srcCSC[i]; int j = i - 1;
            while (j >= p0 && g_srcCSC[j] > x) { g_srcCSC[j + 1] = g_srcCSC[j]; j--; }
            g_srcCSC[j + 1] = x;
        }
        int deg = p1 - p0;
        int pos = g_ppos[id];
        int g = pos >> 5, lane = pos & 31;
        int base = g_ellbase[g];
        int gm = (g_ellbase[g + 1] - base) >> 5;
        for (int p = 0; p < gm; p++)
            g_ell[base + (p << 5) + lane] =
                (p < deg) ? (unsigned short)(g_srcCSC[p0 + p] << 4)
                          : (unsigned short)(2048 << 4);
    } else {
        int r = id - NN;
        int p0 = g_rowptr[r], p1 = g_rowptr[r + 1];
        for (int i = p0 + 1; i < p1; i++) {
            int x = g_dst[i]; int j = i - 1;
            while (j >= p0 && g_dst[j] > x) { g_dst[j + 1] = g_dst[j]; j--; }
            g_dst[j + 1] = x;
        }
    }
}

// ---------------- persistent push + fused topk/output ----------------
__global__ void __launch_bounds__(NTHREADS, 2)
k_push(const float* __restrict__ X, float* __restrict__ out) {
    extern __shared__ float sh[];
    float* pv = sh;                      // [8196] weights (dense mode); [8192..]=0 pad
    int* cand = (int*)sh;                // alias: candidate list (LIST mode)
    float* cur = pv + ROWS * NN + 4;     // [8192] residual
    float* Pp = cur + ROWS * NN;         // [8192] P accumulator
    int* lk = (int*)(Pp + ROWS * NN);    // [LISTCAP] frontier entries
    float* lw = (float*)(lk + LISTCAP);  // [LISTCAP] frontier weights
    __shared__ int s_a, s_b, s_of, s_tile;
    __shared__ float s_redv[16];
    __shared__ int s_redi[16];
    __shared__ float s_tv[ROWS][TOPK];
    __shared__ int s_ti[ROWS][TOPK];

    float4* pv4 = (float4*)pv;
    float4* cur4 = (float4*)cur;
    float4* Pp4 = (float4*)Pp;

    const int tid = threadIdx.x;
    const int lane = tid & 31;
    const int wid = tid >> 5;
    const unsigned FULL = 0xffffffffu;

    while (true) {
        __syncthreads();
        if (tid == 0) s_tile = atomicAdd(&g_work, 1);
        __syncthreads();
        const int t = s_tile;
        if (t >= NTILES) break;
        const int row0 = t * ROWS;

        // ---- init tile state
        if (tid == 0) pv4[2048] = make_float4(0.f, 0.f, 0.f, 0.f);  // ELL pad (never aliased)
#pragma unroll
        for (int m = 0; m < NN / NTHREADS; m++) {
            int j = tid + NTHREADS * m;
            float4 z = make_float4(0.f, 0.f, 0.f, 0.f);
            Pp4[j] = z;
            int d = j - row0;
            if (d >= 0 && d < ROWS) ((float*)&z)[d] = 1.f;
            cur4[j] = z;
        }
        if (tid < ROWS) cand[tid] = ((row0 + tid) << 2) | tid;
        int mode = 0;         // 0 = LIST, 1 = SCAN
        int ccnt = ROWS;

        for (int iter = 0; iter < MAXIT; iter++) {
            if (mode == 0) {
                // ---- pass 0: upper-bound count over candidates (no mutation)
                if (tid == 0) s_a = 0;
                __syncthreads();
                int ub = 0;
                for (int l = tid; l < ccnt; l += NTHREADS)
                    ub += (cur[cand[l]] >= RMAXF);
                ub = __reduce_add_sync(FULL, ub);
                if (lane == 0 && ub) atomicAdd(&s_a, ub);
                __syncthreads();
                int ubt = s_a;
                __syncthreads();   // FIX: all threads read s_a before it is reset below
                if (ubt == 0) break;
                if (ubt > SPARSE_T) { mode = 1; continue; }

                // ---- pass 1: claim candidates (atomicExch dedupe), build frontier
                if (tid == 0) s_a = 0;
                __syncthreads();
                for (int l0 = 0; l0 < ccnt; l0 += NTHREADS) {
                    int l = l0 + tid;
                    bool act = l < ccnt;
                    int e = act ? cand[l] : 0;
                    float val = 0.f;
                    if (act) val = atomicExch(&cur[e], 0.f);
                    bool push = act && (val >= RMAXF);
                    if (act && !push && val > 0.f) cur[e] = val;   // restore keeps
                    if (push) Pp[e] += 0.5f * val;
                    unsigned msk = __ballot_sync(FULL, push);
                    if (msk) {
                        int base = 0;
                        if (lane == 0) base = atomicAdd(&s_a, __popc(msk));
                        base = __shfl_sync(FULL, base, 0);
                        if (push) {
                            int pos = base + __popc(msk & ((1u << lane) - 1));
                            lk[pos] = e;
                            lw[pos] = val * __ldg(&g_halfinv[e >> 2]);
                        }
                    }
                }
                __syncthreads();
                int fcnt = s_a;
                if (fcnt == 0) break;

                // ---- pass 2: scatter frontier, append candidates
                if (tid == 0) { s_b = 0; s_of = 0; }
                __syncthreads();
                for (int l0 = 0; l0 < fcnt; l0 += NTHREADS) {
                    int l = l0 + tid;
                    bool act = l < fcnt;
                    int e = act ? lk[l] : 0;
                    int k = e >> 2, r = e & 3;
                    float w = act ? lw[l] : 0.f;
                    int p0 = 0, deg = 0;
                    if (act) { p0 = __ldg(&g_rowptr[k]); deg = __ldg(&g_rowptr[k + 1]) - p0; }
                    int incl = deg;
#pragma unroll
                    for (int off = 1; off < 32; off <<= 1) {
                        int n = __shfl_up_sync(FULL, incl, off);
                        if (lane >= off) incl += n;
                    }
                    int total = __shfl_sync(FULL, incl, 31);
                    int wbase = 0;
                    if (total) {
                        if (lane == 0) wbase = atomicAdd(&s_b, total);
                        wbase = __shfl_sync(FULL, wbase, 0);
                    }
                    bool ok = (wbase + total <= CCAP);
                    if (!ok && lane == 0) s_of = 1;
                    int mybase = wbase + incl - deg;
                    for (int p = 0; p < deg; p++) {
                        int d = (__ldg(&g_dst[p0 + p]) << 2) | r;
                        atomicAdd(&cur[d], w);
                        if (ok) cand[mybase + p] = d;
                    }
                }
                __syncthreads();
                if (s_of) { mode = 1; }
                else { ccnt = s_b; if (ccnt == 0) break; }
            } else {
                // ---- SCAN mode: phase A full scan
                if (tid == 0) s_a = 0;
                __syncthreads();
#pragma unroll
                for (int m = 0; m < NN / NTHREADS; m++) {
                    int j = tid + NTHREADS * m;
                    float4 v = cur4[j];
                    float h = __ldg(&g_halfinv[j]);
                    bool px = v.x >= RMAXF, py = v.y >= RMAXF,
                         pz = v.z >= RMAXF, pw = v.w >= RMAXF;
                    float4 pvv = make_float4(px ? v.x * h : 0.f, py ? v.y * h : 0.f,
                                             pz ? v.z * h : 0.f, pw ? v.w * h : 0.f);
                    pv4[j] = pvv;
                    if (px | py | pz | pw) {
                        float4 p = Pp4[j];
                        if (px) { p.x += 0.5f * v.x; v.x = 0.f; }
                        if (py) { p.y += 0.5f * v.y; v.y = 0.f; }
                        if (pz) { p.z += 0.5f * v.z; v.z = 0.f; }
                        if (pw) { p.w += 0.5f * v.w; v.w = 0.f; }
                        Pp4[j] = p;
                        cur4[j] = v;
                    }
                    bool pr[4] = {px, py, pz, pw};
                    float wv[4] = {pvv.x, pvv.y, pvv.z, pvv.w};
#pragma unroll
                    for (int r = 0; r < 4; r++) {
                        unsigned msk = __ballot_sync(FULL, pr[r]);
                        if (msk) {
                            int base = 0;
                            if (lane == 0) base = atomicAdd(&s_a, __popc(msk));
                            base = __shfl_sync(FULL, base, 0);
                            if (pr[r]) {
                                int pos = base + __popc(msk & ((1u << lane) - 1));
                                if (pos < LISTCAP) { lk[pos] = (j << 2) | r; lw[pos] = wv[r]; }
                            }
                        }
                    }
                }
                __syncthreads();
                const int cnt = s_a;
                if (cnt == 0) break;

                if (cnt > SPARSE_T) {
                    // ---- dense: ELL gather (clobbers cand alias; rebuilt on exit to LIST)
#pragma unroll
                    for (int m = 0; m < NGRP / (NTHREADS / 32); m++) {
                        int g = wid + (NTHREADS / 32) * m;
                        int jr = __ldg(&g_perm[(g << 5) + lane]);
                        int base = __ldg(&g_ellbase[g]);
                        int gm = (__ldg(&g_ellbase[g + 1]) - base) >> 5;
                        const unsigned short* ep = g_ell + base + lane;
                        float4 acc = cur4[jr];
#pragma unroll 4
                        for (int p = 0; p < gm; p++) {
                            int off = ep[p << 5];
                            float4 v = *(const float4*)((const char*)pv + off);
                            acc.x += v.x; acc.y += v.y; acc.z += v.z; acc.w += v.w;
                        }
                        cur4[jr] = acc;
                    }
                    __syncthreads();
                    // mode stays SCAN
                } else {
                    // ---- sparse: scatter + append candidates -> LIST mode
                    if (tid == 0) { s_b = 0; s_of = 0; }
                    __syncthreads();
                    for (int l0 = 0; l0 < cnt; l0 += NTHREADS) {
                        int l = l0 + tid;
                        bool act = l < cnt;
                        int e = act ? lk[l] : 0;
                        int k = e >> 2, r = e & 3;
                        float w = act ? lw[l] : 0.f;
                        int p0 = 0, deg = 0;
                        if (act) { p0 = __ldg(&g_rowptr[k]); deg = __ldg(&g_rowptr[k + 1]) - p0; }
                        int incl = deg;
#pragma unroll
                        for (int off = 1; off < 32; off <<= 1) {
                            int n = __shfl_up_sync(FULL, incl, off);
                            if (lane >= off) incl += n;
                        }
                        int total = __shfl_sync(FULL, incl, 31);
                        int wbase = 0;
                        if (total) {
                            if (lane == 0) wbase = atomicAdd(&s_b, total);
                            wbase = __shfl_sync(FULL, wbase, 0);
                        }
                        bool ok = (wbase + total <= CCAP);
                        if (!ok && lane == 0) s_of = 1;
                        int mybase = wbase + incl - deg;
                        for (int p = 0; p < deg; p++) {
                            int d = (__ldg(&g_dst[p0 + p]) << 2) | r;
                            atomicAdd(&cur[d], w);
                            if (ok) cand[mybase + p] = d;
                        }
                    }
                    __syncthreads();
                    if (!s_of) { ccnt = s_b; mode = 0; if (ccnt == 0) break; }
                }
            }
        }
        __syncthreads();

        // ---- fused top-k per row (128 threads per row)
        const int rg = tid >> 7;
        const int tl = tid & 127;
        for (int q = 0; q < TOPK; q++) {
            float bv = -1.f; int bi = NN;
#pragma unroll
            for (int m = 0; m < NN / 128; m++) {
                int j = tl + 128 * m;
                float v = Pp[(j << 2) | rg];
                if (v > bv || (v == bv && j < bi)) { bv = v; bi = j; }
            }
#pragma unroll
            for (int off = 16; off; off >>= 1) {
                float ov = __shfl_down_sync(FULL, bv, off);
                int oi = __shfl_down_sync(FULL, bi, off);
                if (ov > bv || (ov == bv && oi < bi)) { bv = ov; bi = oi; }
            }
            if (lane == 0) { s_redv[wid] = bv; s_redi[wid] = bi; }
            __syncthreads();
            if (tl == 0) {
                float v0 = s_redv[4 * rg]; int i0 = s_redi[4 * rg];
#pragma unroll
                for (int w = 1; w < 4; w++) {
                    float v1 = s_redv[4 * rg + w]; int i1 = s_redi[4 * rg + w];
                    if (v1 > v0 || (v1 == v0 && i1 < i0)) { v0 = v1; i0 = i1; }
                }
                s_tv[rg][q] = v0; s_ti[rg][q] = i0;
                Pp[(i0 << 2) | rg] = -2.f;
            }
            __syncthreads();
        }

        // ---- output GEMV
        const float4* X4 = (const float4*)X;
        float4* out4 = (float4*)out;
#pragma unroll
        for (int m = 0; m < DF / 4 / 128; m++) {
            int col = tl + 128 * m;
            float4 acc = make_float4(0.f, 0.f, 0.f, 0.f);
#pragma unroll
            for (int q = 0; q < TOPK; q++) {
                float w = s_tv[rg][q];
                float4 x = __ldg(&X4[(size_t)s_ti[rg][q] * (DF / 4) + col]);
                acc.x += w * x.x; acc.y += w * x.y;
                acc.z += w * x.z; acc.w += w * x.w;
            }
            out4[(size_t)(row0 + rg) * (DF / 4) + col] = acc;
        }
    }
}

// ---------------- launch ----------------
extern "C" void kernel_launch(void* const* d_in, const int* in_sizes, int n_in,
                              void* d_out, int out_size) {
    const float* X;
    const int* ei;
    if (in_sizes[0] == 2 * NE) { ei = (const int*)d_in[0]; X = (const float*)d_in[1]; }
    else { X = (const float*)d_in[0]; ei = (const int*)d_in[1]; }
    float* out = (float*)d_out;

    const int smem = (ROWS * NN + 4 + 2 * ROWS * NN) * sizeof(float)  // pv/cand,cur,Pp
                   + LISTCAP * sizeof(int) + LISTCAP * sizeof(float); // lk,lw ~104.2KB
    cudaFuncSetAttribute(k_push, cudaFuncAttributeMaxDynamicSharedMemorySize, smem);

    k_zero<<<(NN + 255) / 256, 256>>>();
    k_count<<<NE / 256, 256>>>(ei);
    k_scanperm<<<1, 256>>>();
    k_fill<<<NE / 256, 256>>>(ei);
    k_build<<<16, 256>>>();
    k_push<<<GRID, NTHREADS, smem>>>(X, out);
}